// round 1
// baseline (speedup 1.0000x reference)
#include <cuda_runtime.h>
#include <math.h>

// Problem shape (fixed by the dataset)
#define BATCH   4
#define S_LEN   2048
#define DMODEL  1024
#define NHEAD   16
#define HD      64
#define MTOK    (BATCH * S_LEN)        // 8192 token rows

// Scratch (device globals: allocation-free)
__device__ float g_qkv[(size_t)MTOK * 3 * DMODEL];   // [B*S, 3072] : q|k|v thirds
__device__ float g_attn[(size_t)MTOK * DMODEL];      // [B*S, 1024]

// ---------------------------------------------------------------------------
// SGEMM with bias: C[M,N] = A[M,K] @ B[K,N] + bias[N]
// 128x128 tile, BK=8, 256 threads, 8x8 micro-tile (two 4-wide halves)
// ---------------------------------------------------------------------------
#define BM 128
#define BN 128
#define BK 8

__global__ __launch_bounds__(256) void sgemm_bias_kernel(
    const float* __restrict__ A, const float* __restrict__ B,
    const float* __restrict__ bias, float* __restrict__ C,
    int M, int N, int K)
{
    __shared__ float As[BK][BM];
    __shared__ float Bs[BK][BN];

    const int tid = threadIdx.x;
    const int bm = blockIdx.y * BM;
    const int bn = blockIdx.x * BN;

    // global-load assignments
    const int a_row = tid >> 1;          // 0..127
    const int a_k   = (tid & 1) << 2;    // 0 or 4
    const int b_k   = tid >> 5;          // 0..7
    const int b_n   = (tid & 31) << 2;   // 0..124

    // compute assignments: rows {ry..ry+3, 64+ry..}, cols {cx..cx+3, 64+cx..}
    const int ry = (tid >> 4) << 2;      // 0..60
    const int cx = (tid & 15) << 2;      // 0..60

    float acc[8][8];
    #pragma unroll
    for (int i = 0; i < 8; i++)
        #pragma unroll
        for (int j = 0; j < 8; j++) acc[i][j] = 0.0f;

    const float* Ag = A + (size_t)(bm + a_row) * K + a_k;
    const float* Bg = B + (size_t)b_k * N + bn + b_n;

    for (int kt = 0; kt < K; kt += BK) {
        float4 av = *(const float4*)(Ag + kt);
        float4 bv = *(const float4*)(Bg + (size_t)kt * N);
        __syncthreads();
        As[a_k + 0][a_row] = av.x;
        As[a_k + 1][a_row] = av.y;
        As[a_k + 2][a_row] = av.z;
        As[a_k + 3][a_row] = av.w;
        *(float4*)&Bs[b_k][b_n] = bv;
        __syncthreads();

        #pragma unroll
        for (int k = 0; k < BK; k++) {
            float a[8], b[8];
            *(float4*)(a)     = *(const float4*)&As[k][ry];
            *(float4*)(a + 4) = *(const float4*)&As[k][ry + 64];
            *(float4*)(b)     = *(const float4*)&Bs[k][cx];
            *(float4*)(b + 4) = *(const float4*)&Bs[k][cx + 64];
            #pragma unroll
            for (int i = 0; i < 8; i++)
                #pragma unroll
                for (int j = 0; j < 8; j++)
                    acc[i][j] += a[i] * b[j];
        }
    }

    // epilogue: add bias, float4 stores
    #pragma unroll
    for (int ih = 0; ih < 2; ih++) {
        #pragma unroll
        for (int ii = 0; ii < 4; ii++) {
            int r = bm + ih * 64 + ry + ii;
            int ai = ih * 4 + ii;
            #pragma unroll
            for (int jh = 0; jh < 2; jh++) {
                int c = bn + jh * 64 + cx;
                float4 bb = *(const float4*)&bias[c];
                float4 o;
                o.x = acc[ai][jh * 4 + 0] + bb.x;
                o.y = acc[ai][jh * 4 + 1] + bb.y;
                o.z = acc[ai][jh * 4 + 2] + bb.z;
                o.w = acc[ai][jh * 4 + 3] + bb.w;
                *(float4*)&C[(size_t)r * N + c] = o;
            }
        }
    }
}

// ---------------------------------------------------------------------------
// Flash attention (fp32, causal). Block = one (b,h,q-tile of 64 rows).
// 256 threads: ty=tid/16 (row group), tx=tid%16 (col group).
// Thread owns rows {ty+16i} and cols {tx+16j}, i,j in 0..3.
// smem: Qs[64][64], Ks[64][68] (reused as P), Vs[64][64] -> 50176 B dynamic.
// ---------------------------------------------------------------------------
#define KSTR 68
#define ATTN_SMEM_BYTES ((64*64 + 64*KSTR + 64*64) * 4)

__device__ __forceinline__ float grp_max16(float v) {
    v = fmaxf(v, __shfl_xor_sync(0xffffffffu, v, 1));
    v = fmaxf(v, __shfl_xor_sync(0xffffffffu, v, 2));
    v = fmaxf(v, __shfl_xor_sync(0xffffffffu, v, 4));
    v = fmaxf(v, __shfl_xor_sync(0xffffffffu, v, 8));
    return v;
}
__device__ __forceinline__ float grp_sum16(float v) {
    v += __shfl_xor_sync(0xffffffffu, v, 1);
    v += __shfl_xor_sync(0xffffffffu, v, 2);
    v += __shfl_xor_sync(0xffffffffu, v, 4);
    v += __shfl_xor_sync(0xffffffffu, v, 8);
    return v;
}

__global__ __launch_bounds__(256) void attn_kernel()
{
    extern __shared__ float sm[];
    float* Qs = sm;                  // [64][64]
    float* Ks = sm + 64 * 64;        // [64][KSTR], also reused as P tile
    float* Vs = Ks + 64 * KSTR;      // [64][64]

    const int tid = threadIdx.x;
    const int ty = tid >> 4;         // 0..15
    const int tx = tid & 15;         // 0..15

    const int qt = blockIdx.x;       // 0..31
    const int bh = blockIdx.y;       // 0..63
    const int b  = bh >> 4;
    const int h  = bh & (NHEAD - 1);

    const int q0 = qt * 64;
    const float scale = 0.125f;      // 1/sqrt(64)
    const float NEG = -1e30f;

    // load Q tile: 64 rows x 64 dims
    {
        int row = tid >> 2;
        int c0  = (tid & 3) << 4;
        const float* src = g_qkv + ((size_t)(b * S_LEN + q0 + row)) * (3 * DMODEL)
                         + h * HD + c0;
        float* dst = Qs + row * 64 + c0;
        #pragma unroll
        for (int v = 0; v < 4; v++)
            *(float4*)(dst + v * 4) = *(const float4*)(src + v * 4);
    }

    float o[4][4], m[4], l[4];
    #pragma unroll
    for (int i = 0; i < 4; i++) {
        m[i] = NEG; l[i] = 0.0f;
        #pragma unroll
        for (int j = 0; j < 4; j++) o[i][j] = 0.0f;
    }

    for (int kt = 0; kt <= qt; kt++) {
        const int k0 = kt * 64;
        __syncthreads();   // previous iteration's P/V reads done
        // load K & V tiles
        {
            int row = tid >> 2;
            int c0  = (tid & 3) << 4;
            const float* kb = g_qkv + ((size_t)(b * S_LEN + k0 + row)) * (3 * DMODEL)
                            + DMODEL + h * HD + c0;
            const float* vb = kb + DMODEL;
            float* kd = Ks + row * KSTR + c0;
            float* vd = Vs + row * 64 + c0;
            #pragma unroll
            for (int v = 0; v < 4; v++) {
                *(float4*)(kd + v * 4) = *(const float4*)(kb + v * 4);
                *(float4*)(vd + v * 4) = *(const float4*)(vb + v * 4);
            }
        }
        __syncthreads();

        // GEMM1: s = Q @ K^T  (64x64x64)
        float s[4][4];
        #pragma unroll
        for (int i = 0; i < 4; i++)
            #pragma unroll
            for (int j = 0; j < 4; j++) s[i][j] = 0.0f;

        #pragma unroll
        for (int kk = 0; kk < 64; kk += 4) {
            float4 qv[4], kv[4];
            #pragma unroll
            for (int i = 0; i < 4; i++)
                qv[i] = *(const float4*)&Qs[(ty + 16 * i) * 64 + kk];
            #pragma unroll
            for (int j = 0; j < 4; j++)
                kv[j] = *(const float4*)&Ks[(tx + 16 * j) * KSTR + kk];
            #pragma unroll
            for (int i = 0; i < 4; i++)
                #pragma unroll
                for (int j = 0; j < 4; j++)
                    s[i][j] += qv[i].x * kv[j].x + qv[i].y * kv[j].y
                             + qv[i].z * kv[j].z + qv[i].w * kv[j].w;
        }

        // scale + causal mask (only diagonal tile needs masking)
        #pragma unroll
        for (int i = 0; i < 4; i++)
            #pragma unroll
            for (int j = 0; j < 4; j++) s[i][j] *= scale;
        if (kt == qt) {
            #pragma unroll
            for (int i = 0; i < 4; i++) {
                int qg = ty + 16 * i;
                #pragma unroll
                for (int j = 0; j < 4; j++) {
                    int kg = tx + 16 * j;
                    if (kg > qg) s[i][j] = NEG;
                }
            }
        }

        // online softmax per row
        #pragma unroll
        for (int i = 0; i < 4; i++) {
            float rm = fmaxf(fmaxf(s[i][0], s[i][1]), fmaxf(s[i][2], s[i][3]));
            rm = grp_max16(rm);
            float mn = fmaxf(m[i], rm);
            float corr = __expf(m[i] - mn);
            float rs = 0.0f;
            #pragma unroll
            for (int j = 0; j < 4; j++) {
                s[i][j] = __expf(s[i][j] - mn);
                rs += s[i][j];
            }
            rs = grp_sum16(rs);
            l[i] = l[i] * corr + rs;
            m[i] = mn;
            #pragma unroll
            for (int j = 0; j < 4; j++) o[i][j] *= corr;
        }

        __syncthreads();   // all GEMM1 reads of Ks done
        // store P into Ks slot
        #pragma unroll
        for (int i = 0; i < 4; i++)
            #pragma unroll
            for (int j = 0; j < 4; j++)
                Ks[(ty + 16 * i) * KSTR + tx + 16 * j] = s[i][j];
        __syncthreads();

        // GEMM2: O += P @ V  (64x64x64)
        #pragma unroll
        for (int c = 0; c < 64; c += 4) {
            float pf[4][4];
            #pragma unroll
            for (int i = 0; i < 4; i++) {
                float4 pv = *(const float4*)&Ks[(ty + 16 * i) * KSTR + c];
                pf[i][0] = pv.x; pf[i][1] = pv.y; pf[i][2] = pv.z; pf[i][3] = pv.w;
            }
            #pragma unroll
            for (int cc = 0; cc < 4; cc++) {
                float vv[4];
                #pragma unroll
                for (int j = 0; j < 4; j++)
                    vv[j] = Vs[(c + cc) * 64 + tx + 16 * j];
                #pragma unroll
                for (int i = 0; i < 4; i++)
                    #pragma unroll
                    for (int j = 0; j < 4; j++)
                        o[i][j] += pf[i][cc] * vv[j];
            }
        }
    }

    // write normalized output: [B,S, h*64+d]
    #pragma unroll
    for (int i = 0; i < 4; i++) {
        float inv = 1.0f / l[i];
        int q = q0 + ty + 16 * i;
        float* dst = g_attn + ((size_t)(b * S_LEN + q)) * DMODEL + h * HD;
        #pragma unroll
        for (int j = 0; j < 4; j++)
            dst[tx + 16 * j] = o[i][j] * inv;
    }
}

// ---------------------------------------------------------------------------
// kernel_launch
// inputs (metadata order): x, w_qkv, b_qkv, w_proj, b_proj
// ---------------------------------------------------------------------------
extern "C" void kernel_launch(void* const* d_in, const int* in_sizes, int n_in,
                              void* d_out, int out_size)
{
    const float* x      = (const float*)d_in[0];
    const float* w_qkv  = (const float*)d_in[1];
    const float* b_qkv  = (const float*)d_in[2];
    const float* w_proj = (const float*)d_in[3];
    const float* b_proj = (const float*)d_in[4];
    float* out = (float*)d_out;

    void* qkv_ptr = nullptr;
    void* attn_ptr = nullptr;
    cudaGetSymbolAddress(&qkv_ptr, g_qkv);
    cudaGetSymbolAddress(&attn_ptr, g_attn);

    cudaFuncSetAttribute(attn_kernel,
                         cudaFuncAttributeMaxDynamicSharedMemorySize,
                         ATTN_SMEM_BYTES);

    // 1) QKV projection: [8192,1024] @ [1024,3072] + b
    {
        dim3 grid(3 * DMODEL / BN, MTOK / BM);
        sgemm_bias_kernel<<<grid, 256>>>(x, w_qkv, b_qkv, (float*)qkv_ptr,
                                         MTOK, 3 * DMODEL, DMODEL);
    }

    // 2) causal flash attention
    {
        dim3 grid(S_LEN / 64, BATCH * NHEAD);
        attn_kernel<<<grid, 256, ATTN_SMEM_BYTES>>>();
    }

    // 3) output projection: [8192,1024] @ [1024,1024] + b
    {
        dim3 grid(DMODEL / BN, MTOK / BM);
        sgemm_bias_kernel<<<grid, 256>>>((const float*)attn_ptr, w_proj, b_proj,
                                         out, MTOK, DMODEL, DMODEL);
    }
}

// round 3
// speedup vs baseline: 1.4009x; 1.4009x over previous
#include <cuda_runtime.h>
#include <math.h>
#include <stdint.h>

// Problem shape (fixed by the dataset)
#define BATCH   4
#define S_LEN   2048
#define DMODEL  1024
#define NHEAD   16
#define HD      64
#define MTOK    (BATCH * S_LEN)        // 8192 token rows

// ---------------------------------------------------------------------------
// Scratch (device globals: allocation-free)
// ---------------------------------------------------------------------------
__device__ uint32_t g_x_t[(size_t)MTOK * DMODEL];            // x as tf32
__device__ uint32_t g_wqkv_t[(size_t)DMODEL * 3 * DMODEL];   // w_qkv [K,N] tf32
__device__ uint32_t g_wproj_t[(size_t)DMODEL * DMODEL];      // w_proj [K,N] tf32
__device__ float    g_qkv[(size_t)MTOK * 3 * DMODEL];        // fp32 qkv
__device__ uint32_t g_attn[(size_t)MTOK * DMODEL];           // attn out as tf32

__device__ __forceinline__ uint32_t f32_to_tf32(float v) {
    uint32_t b;
    asm("cvt.rna.tf32.f32 %0, %1;" : "=r"(b) : "f"(v));
    return b;
}

__device__ __forceinline__ void mma_tf32(float* c, const uint32_t* a,
                                         const uint32_t* b) {
    asm volatile(
        "mma.sync.aligned.m16n8k8.row.col.f32.tf32.tf32.f32 "
        "{%0,%1,%2,%3}, {%4,%5,%6,%7}, {%8,%9}, {%0,%1,%2,%3};"
        : "+f"(c[0]), "+f"(c[1]), "+f"(c[2]), "+f"(c[3])
        : "r"(a[0]), "r"(a[1]), "r"(a[2]), "r"(a[3]), "r"(b[0]), "r"(b[1]));
}

// ---------------------------------------------------------------------------
// tf32 tensor-core GEMM (mma.sync): C[M,N] = A[M,K] @ B[K,N] + bias[N]
// Block 128x128, BK=16, 256 threads (8 warps: 2 m x 4 n), warp tile 64x32.
// As stored k-major [BK][136] (pad 8 => fragment reads conflict-free),
// Bs stored [BK][136] row-major chunks of B.
// ---------------------------------------------------------------------------
#define BKC 16
#define SSTR 136

__global__ __launch_bounds__(256) void tf32_gemm_kernel(
    const uint32_t* __restrict__ A, const uint32_t* __restrict__ B,
    const float* __restrict__ bias, float* __restrict__ C,
    int M, int N, int K)
{
    __shared__ uint32_t As[BKC][SSTR];
    __shared__ uint32_t Bs[BKC][SSTR];

    const int tid  = threadIdx.x;
    const int wid  = tid >> 5;
    const int lane = tid & 31;
    const int g = lane >> 2;          // 0..7
    const int q = lane & 3;           // 0..3

    const int wm = (wid >> 2) << 6;   // 0 or 64
    const int wn = (wid & 3) << 5;    // 0,32,64,96

    const int bm = blockIdx.y << 7;
    const int bn = blockIdx.x << 7;

    // global->smem assignments
    const int am = tid >> 1;              // 0..127
    const int ak = (tid & 1) << 3;        // 0 or 8
    const int bk = tid >> 4;              // 0..15
    const int bn8 = (tid & 15) << 3;      // 0..120

    float acc[4][4][4];
    #pragma unroll
    for (int mi = 0; mi < 4; mi++)
        #pragma unroll
        for (int ni = 0; ni < 4; ni++)
            #pragma unroll
            for (int r = 0; r < 4; r++) acc[mi][ni][r] = 0.0f;

    const uint32_t* Ag = A + (size_t)(bm + am) * K + ak;
    const uint32_t* Bg = B + (size_t)bk * N + bn + bn8;

    for (int kt = 0; kt < K; kt += BKC) {
        uint4 ra0 = *(const uint4*)(Ag + kt);
        uint4 ra1 = *(const uint4*)(Ag + kt + 4);
        uint4 rb0 = *(const uint4*)(Bg + (size_t)kt * N);
        uint4 rb1 = *(const uint4*)(Bg + (size_t)kt * N + 4);
        __syncthreads();
        As[ak + 0][am] = ra0.x; As[ak + 1][am] = ra0.y;
        As[ak + 2][am] = ra0.z; As[ak + 3][am] = ra0.w;
        As[ak + 4][am] = ra1.x; As[ak + 5][am] = ra1.y;
        As[ak + 6][am] = ra1.z; As[ak + 7][am] = ra1.w;
        *(uint4*)&Bs[bk][bn8]     = rb0;
        *(uint4*)&Bs[bk][bn8 + 4] = rb1;
        __syncthreads();

        #pragma unroll
        for (int k8 = 0; k8 < BKC; k8 += 8) {
            uint32_t af[4][4], bf[4][2];
            #pragma unroll
            for (int mi = 0; mi < 4; mi++) {
                int m = wm + (mi << 4) + g;
                af[mi][0] = As[k8 + q][m];
                af[mi][1] = As[k8 + q][m + 8];
                af[mi][2] = As[k8 + q + 4][m];
                af[mi][3] = As[k8 + q + 4][m + 8];
            }
            #pragma unroll
            for (int ni = 0; ni < 4; ni++) {
                int n = wn + (ni << 3) + g;
                bf[ni][0] = Bs[k8 + q][n];
                bf[ni][1] = Bs[k8 + q + 4][n];
            }
            #pragma unroll
            for (int mi = 0; mi < 4; mi++)
                #pragma unroll
                for (int ni = 0; ni < 4; ni++)
                    mma_tf32(acc[mi][ni], af[mi], bf[ni]);
        }
    }

    // epilogue: c0,c1 at (m, n..n+1); c2,c3 at (m+8, n..n+1)
    #pragma unroll
    for (int mi = 0; mi < 4; mi++) {
        int m = bm + wm + (mi << 4) + g;
        #pragma unroll
        for (int ni = 0; ni < 4; ni++) {
            int n = bn + wn + (ni << 3) + (q << 1);
            float2 bb = *(const float2*)&bias[n];
            float2 o0, o1;
            o0.x = acc[mi][ni][0] + bb.x;
            o0.y = acc[mi][ni][1] + bb.y;
            o1.x = acc[mi][ni][2] + bb.x;
            o1.y = acc[mi][ni][3] + bb.y;
            *(float2*)&C[(size_t)m * N + n]       = o0;
            *(float2*)&C[(size_t)(m + 8) * N + n] = o1;
        }
    }
}

// ---------------------------------------------------------------------------
// Elementwise fp32 -> tf32 (rna) conversion
// ---------------------------------------------------------------------------
__global__ void cvt_tf32_kernel(const float4* __restrict__ src,
                                uint4* __restrict__ dst, int n4)
{
    int i = blockIdx.x * blockDim.x + threadIdx.x;
    if (i < n4) {
        float4 v = src[i];
        uint4 o;
        o.x = f32_to_tf32(v.x); o.y = f32_to_tf32(v.y);
        o.z = f32_to_tf32(v.z); o.w = f32_to_tf32(v.w);
        dst[i] = o;
    }
}

// ---------------------------------------------------------------------------
// Flash attention (fp32, causal); output written as tf32 for proj GEMM.
// ---------------------------------------------------------------------------
#define KSTR 68
#define ATTN_SMEM_BYTES ((64*64 + 64*KSTR + 64*64) * 4)

__device__ __forceinline__ float grp_max16(float v) {
    v = fmaxf(v, __shfl_xor_sync(0xffffffffu, v, 1));
    v = fmaxf(v, __shfl_xor_sync(0xffffffffu, v, 2));
    v = fmaxf(v, __shfl_xor_sync(0xffffffffu, v, 4));
    v = fmaxf(v, __shfl_xor_sync(0xffffffffu, v, 8));
    return v;
}
__device__ __forceinline__ float grp_sum16(float v) {
    v += __shfl_xor_sync(0xffffffffu, v, 1);
    v += __shfl_xor_sync(0xffffffffu, v, 2);
    v += __shfl_xor_sync(0xffffffffu, v, 4);
    v += __shfl_xor_sync(0xffffffffu, v, 8);
    return v;
}

__global__ __launch_bounds__(256) void attn_kernel()
{
    extern __shared__ float sm[];
    float* Qs = sm;                  // [64][64]
    float* Ks = sm + 64 * 64;        // [64][KSTR], reused as P
    float* Vs = Ks + 64 * KSTR;      // [64][64]

    const int tid = threadIdx.x;
    const int ty = tid >> 4;
    const int tx = tid & 15;

    const int qt = blockIdx.x;
    const int bh = blockIdx.y;
    const int b  = bh >> 4;
    const int h  = bh & (NHEAD - 1);

    const int q0 = qt * 64;
    const float scale = 0.125f;
    const float NEG = -1e30f;

    {
        int row = tid >> 2;
        int c0  = (tid & 3) << 4;
        const float* src = g_qkv + ((size_t)(b * S_LEN + q0 + row)) * (3 * DMODEL)
                         + h * HD + c0;
        float* dst = Qs + row * 64 + c0;
        #pragma unroll
        for (int v = 0; v < 4; v++)
            *(float4*)(dst + v * 4) = *(const float4*)(src + v * 4);
    }

    float o[4][4], m[4], l[4];
    #pragma unroll
    for (int i = 0; i < 4; i++) {
        m[i] = NEG; l[i] = 0.0f;
        #pragma unroll
        for (int j = 0; j < 4; j++) o[i][j] = 0.0f;
    }

    for (int kt = 0; kt <= qt; kt++) {
        const int k0 = kt * 64;
        __syncthreads();
        {
            int row = tid >> 2;
            int c0  = (tid & 3) << 4;
            const float* kb = g_qkv + ((size_t)(b * S_LEN + k0 + row)) * (3 * DMODEL)
                            + DMODEL + h * HD + c0;
            const float* vb = kb + DMODEL;
            float* kd = Ks + row * KSTR + c0;
            float* vd = Vs + row * 64 + c0;
            #pragma unroll
            for (int v = 0; v < 4; v++) {
                *(float4*)(kd + v * 4) = *(const float4*)(kb + v * 4);
                *(float4*)(vd + v * 4) = *(const float4*)(vb + v * 4);
            }
        }
        __syncthreads();

        float s[4][4];
        #pragma unroll
        for (int i = 0; i < 4; i++)
            #pragma unroll
            for (int j = 0; j < 4; j++) s[i][j] = 0.0f;

        #pragma unroll
        for (int kk = 0; kk < 64; kk += 4) {
            float4 qv[4], kv[4];
            #pragma unroll
            for (int i = 0; i < 4; i++)
                qv[i] = *(const float4*)&Qs[(ty + 16 * i) * 64 + kk];
            #pragma unroll
            for (int j = 0; j < 4; j++)
                kv[j] = *(const float4*)&Ks[(tx + 16 * j) * KSTR + kk];
            #pragma unroll
            for (int i = 0; i < 4; i++)
                #pragma unroll
                for (int j = 0; j < 4; j++)
                    s[i][j] += qv[i].x * kv[j].x + qv[i].y * kv[j].y
                             + qv[i].z * kv[j].z + qv[i].w * kv[j].w;
        }

        #pragma unroll
        for (int i = 0; i < 4; i++)
            #pragma unroll
            for (int j = 0; j < 4; j++) s[i][j] *= scale;
        if (kt == qt) {
            #pragma unroll
            for (int i = 0; i < 4; i++) {
                int qg = ty + 16 * i;
                #pragma unroll
                for (int j = 0; j < 4; j++) {
                    int kg = tx + 16 * j;
                    if (kg > qg) s[i][j] = NEG;
                }
            }
        }

        #pragma unroll
        for (int i = 0; i < 4; i++) {
            float rm = fmaxf(fmaxf(s[i][0], s[i][1]), fmaxf(s[i][2], s[i][3]));
            rm = grp_max16(rm);
            float mn = fmaxf(m[i], rm);
            float corr = __expf(m[i] - mn);
            float rs = 0.0f;
            #pragma unroll
            for (int j = 0; j < 4; j++) {
                s[i][j] = __expf(s[i][j] - mn);
                rs += s[i][j];
            }
            rs = grp_sum16(rs);
            l[i] = l[i] * corr + rs;
            m[i] = mn;
            #pragma unroll
            for (int j = 0; j < 4; j++) o[i][j] *= corr;
        }

        __syncthreads();
        #pragma unroll
        for (int i = 0; i < 4; i++)
            #pragma unroll
            for (int j = 0; j < 4; j++)
                Ks[(ty + 16 * i) * KSTR + tx + 16 * j] = s[i][j];
        __syncthreads();

        #pragma unroll
        for (int c = 0; c < 64; c += 4) {
            float pf[4][4];
            #pragma unroll
            for (int i = 0; i < 4; i++) {
                float4 pv = *(const float4*)&Ks[(ty + 16 * i) * KSTR + c];
                pf[i][0] = pv.x; pf[i][1] = pv.y; pf[i][2] = pv.z; pf[i][3] = pv.w;
            }
            #pragma unroll
            for (int cc = 0; cc < 4; cc++) {
                float vv[4];
                #pragma unroll
                for (int j = 0; j < 4; j++)
                    vv[j] = Vs[(c + cc) * 64 + tx + 16 * j];
                #pragma unroll
                for (int i = 0; i < 4; i++)
                    #pragma unroll
                    for (int j = 0; j < 4; j++)
                        o[i][j] += pf[i][cc] * vv[j];
            }
        }
    }

    // write normalized output as tf32 (proj GEMM consumes it directly)
    #pragma unroll
    for (int i = 0; i < 4; i++) {
        float inv = 1.0f / l[i];
        int q = q0 + ty + 16 * i;
        uint32_t* dst = g_attn + ((size_t)(b * S_LEN + q)) * DMODEL + h * HD;
        #pragma unroll
        for (int j = 0; j < 4; j++)
            dst[tx + 16 * j] = f32_to_tf32(o[i][j] * inv);
    }
}

// ---------------------------------------------------------------------------
// kernel_launch: x, w_qkv, b_qkv, w_proj, b_proj
// ---------------------------------------------------------------------------
extern "C" void kernel_launch(void* const* d_in, const int* in_sizes, int n_in,
                              void* d_out, int out_size)
{
    const float* x      = (const float*)d_in[0];
    const float* w_qkv  = (const float*)d_in[1];
    const float* b_qkv  = (const float*)d_in[2];
    const float* w_proj = (const float*)d_in[3];
    const float* b_proj = (const float*)d_in[4];
    float* out = (float*)d_out;

    void *x_t, *wqkv_t, *wproj_t, *qkv, *attn;
    cudaGetSymbolAddress(&x_t, g_x_t);
    cudaGetSymbolAddress(&wqkv_t, g_wqkv_t);
    cudaGetSymbolAddress(&wproj_t, g_wproj_t);
    cudaGetSymbolAddress(&qkv, g_qkv);
    cudaGetSymbolAddress(&attn, g_attn);

    cudaFuncSetAttribute(attn_kernel,
                         cudaFuncAttributeMaxDynamicSharedMemorySize,
                         ATTN_SMEM_BYTES);

    // 0) precision-preserving tf32 conversions (cvt.rna) — no transposes needed
    {
        int n4x = MTOK * DMODEL / 4;
        cvt_tf32_kernel<<<(n4x + 255) / 256, 256>>>((const float4*)x, (uint4*)x_t, n4x);
        int n4q = DMODEL * 3 * DMODEL / 4;
        cvt_tf32_kernel<<<(n4q + 255) / 256, 256>>>((const float4*)w_qkv, (uint4*)wqkv_t, n4q);
        int n4p = DMODEL * DMODEL / 4;
        cvt_tf32_kernel<<<(n4p + 255) / 256, 256>>>((const float4*)w_proj, (uint4*)wproj_t, n4p);
    }

    // 1) QKV projection on tensor cores: [8192,1024] @ [1024,3072] + b
    {
        dim3 grid(3 * DMODEL / 128, MTOK / 128);
        tf32_gemm_kernel<<<grid, 256>>>(
            (const uint32_t*)x_t, (const uint32_t*)wqkv_t, b_qkv, (float*)qkv,
            MTOK, 3 * DMODEL, DMODEL);
    }

    // 2) causal flash attention (fp32)
    {
        dim3 grid(S_LEN / 64, BATCH * NHEAD);
        attn_kernel<<<grid, 256, ATTN_SMEM_BYTES>>>();
    }

    // 3) output projection on tensor cores: [8192,1024] @ [1024,1024] + b
    {
        dim3 grid(DMODEL / 128, MTOK / 128);
        tf32_gemm_kernel<<<grid, 256>>>(
            (const uint32_t*)attn, (const uint32_t*)wproj_t, b_proj, out,
            MTOK, DMODEL, DMODEL);
    }
}

// round 4
// speedup vs baseline: 2.5717x; 1.8357x over previous
#include <cuda_runtime.h>
#include <math.h>
#include <stdint.h>

// Problem shape (fixed by the dataset)
#define BATCH   4
#define S_LEN   2048
#define DMODEL  1024
#define NHEAD   16
#define HD      64
#define MTOK    (BATCH * S_LEN)        // 8192 token rows

// ---------------------------------------------------------------------------
// Scratch (device globals: allocation-free)
// ---------------------------------------------------------------------------
__device__ uint32_t g_x_t[(size_t)MTOK * DMODEL];            // x as tf32
__device__ uint32_t g_wqkv_t[(size_t)DMODEL * 3 * DMODEL];   // w_qkv [K,N] tf32
__device__ uint32_t g_wproj_t[(size_t)DMODEL * DMODEL];      // w_proj [K,N] tf32
__device__ float    g_qkv[(size_t)MTOK * 3 * DMODEL];        // fp32 qkv
__device__ uint32_t g_attn[(size_t)MTOK * DMODEL];           // attn out as tf32

__device__ __forceinline__ uint32_t f32_to_tf32(float v) {
    uint32_t b;
    asm("cvt.rna.tf32.f32 %0, %1;" : "=r"(b) : "f"(v));
    return b;
}

__device__ __forceinline__ void mma_tf32(float* c, const uint32_t* a,
                                         const uint32_t* b) {
    asm volatile(
        "mma.sync.aligned.m16n8k8.row.col.f32.tf32.tf32.f32 "
        "{%0,%1,%2,%3}, {%4,%5,%6,%7}, {%8,%9}, {%0,%1,%2,%3};"
        : "+f"(c[0]), "+f"(c[1]), "+f"(c[2]), "+f"(c[3])
        : "r"(a[0]), "r"(a[1]), "r"(a[2]), "r"(a[3]), "r"(b[0]), "r"(b[1]));
}

// ---------------------------------------------------------------------------
// tf32 tensor-core GEMM (mma.sync): C[M,N] = A[M,K] @ B[K,N] + bias[N]
// Block 128x128, BK=16, 256 threads (8 warps: 2 m x 4 n), warp tile 64x32.
// ---------------------------------------------------------------------------
#define BKC 16
#define SSTR 136

__global__ __launch_bounds__(256) void tf32_gemm_kernel(
    const uint32_t* __restrict__ A, const uint32_t* __restrict__ B,
    const float* __restrict__ bias, float* __restrict__ C,
    int M, int N, int K)
{
    __shared__ uint32_t As[BKC][SSTR];
    __shared__ uint32_t Bs[BKC][SSTR];

    const int tid  = threadIdx.x;
    const int wid  = tid >> 5;
    const int lane = tid & 31;
    const int g = lane >> 2;          // 0..7
    const int q = lane & 3;           // 0..3

    const int wm = (wid >> 2) << 6;   // 0 or 64
    const int wn = (wid & 3) << 5;    // 0,32,64,96

    const int bm = blockIdx.y << 7;
    const int bn = blockIdx.x << 7;

    const int am = tid >> 1;
    const int ak = (tid & 1) << 3;
    const int bk = tid >> 4;
    const int bn8 = (tid & 15) << 3;

    float acc[4][4][4];
    #pragma unroll
    for (int mi = 0; mi < 4; mi++)
        #pragma unroll
        for (int ni = 0; ni < 4; ni++)
            #pragma unroll
            for (int r = 0; r < 4; r++) acc[mi][ni][r] = 0.0f;

    const uint32_t* Ag = A + (size_t)(bm + am) * K + ak;
    const uint32_t* Bg = B + (size_t)bk * N + bn + bn8;

    for (int kt = 0; kt < K; kt += BKC) {
        uint4 ra0 = *(const uint4*)(Ag + kt);
        uint4 ra1 = *(const uint4*)(Ag + kt + 4);
        uint4 rb0 = *(const uint4*)(Bg + (size_t)kt * N);
        uint4 rb1 = *(const uint4*)(Bg + (size_t)kt * N + 4);
        __syncthreads();
        As[ak + 0][am] = ra0.x; As[ak + 1][am] = ra0.y;
        As[ak + 2][am] = ra0.z; As[ak + 3][am] = ra0.w;
        As[ak + 4][am] = ra1.x; As[ak + 5][am] = ra1.y;
        As[ak + 6][am] = ra1.z; As[ak + 7][am] = ra1.w;
        *(uint4*)&Bs[bk][bn8]     = rb0;
        *(uint4*)&Bs[bk][bn8 + 4] = rb1;
        __syncthreads();

        #pragma unroll
        for (int k8 = 0; k8 < BKC; k8 += 8) {
            uint32_t af[4][4], bf[4][2];
            #pragma unroll
            for (int mi = 0; mi < 4; mi++) {
                int m = wm + (mi << 4) + g;
                af[mi][0] = As[k8 + q][m];
                af[mi][1] = As[k8 + q][m + 8];
                af[mi][2] = As[k8 + q + 4][m];
                af[mi][3] = As[k8 + q + 4][m + 8];
            }
            #pragma unroll
            for (int ni = 0; ni < 4; ni++) {
                int n = wn + (ni << 3) + g;
                bf[ni][0] = Bs[k8 + q][n];
                bf[ni][1] = Bs[k8 + q + 4][n];
            }
            #pragma unroll
            for (int mi = 0; mi < 4; mi++)
                #pragma unroll
                for (int ni = 0; ni < 4; ni++)
                    mma_tf32(acc[mi][ni], af[mi], bf[ni]);
        }
    }

    #pragma unroll
    for (int mi = 0; mi < 4; mi++) {
        int m = bm + wm + (mi << 4) + g;
        #pragma unroll
        for (int ni = 0; ni < 4; ni++) {
            int n = bn + wn + (ni << 3) + (q << 1);
            float2 bb = *(const float2*)&bias[n];
            float2 o0, o1;
            o0.x = acc[mi][ni][0] + bb.x;
            o0.y = acc[mi][ni][1] + bb.y;
            o1.x = acc[mi][ni][2] + bb.x;
            o1.y = acc[mi][ni][3] + bb.y;
            *(float2*)&C[(size_t)m * N + n]       = o0;
            *(float2*)&C[(size_t)(m + 8) * N + n] = o1;
        }
    }
}

// ---------------------------------------------------------------------------
// Elementwise fp32 -> tf32 (rna) conversion
// ---------------------------------------------------------------------------
__global__ void cvt_tf32_kernel(const float4* __restrict__ src,
                                uint4* __restrict__ dst, int n4)
{
    int i = blockIdx.x * blockDim.x + threadIdx.x;
    if (i < n4) {
        float4 v = src[i];
        uint4 o;
        o.x = f32_to_tf32(v.x); o.y = f32_to_tf32(v.y);
        o.z = f32_to_tf32(v.z); o.w = f32_to_tf32(v.w);
        dst[i] = o;
    }
}

// ---------------------------------------------------------------------------
// Flash attention on tensor cores (tf32 mma.sync), causal.
// Block = 64 q-rows, 4 warps (warp = 16 rows). K-iter tile = 64 keys.
// smem strides: Qs/Ks/Ps = 68 (frag bank = 4g+q, conflict-free),
//               Vs = 72 (frag bank = 8q+g, conflict-free).
// ---------------------------------------------------------------------------
#define AQS 68
#define AVS 72
#define ATTN_SMEM_BYTES ((64*AQS*3 + 64*AVS) * 4)   // Qs,Ks,Ps + Vs = 70656 B

__global__ __launch_bounds__(128) void attn_mma_kernel()
{
    extern __shared__ uint32_t smu[];
    uint32_t* Qs = smu;                    // [64][68]
    uint32_t* Ks = Qs + 64 * AQS;          // [64][68]
    uint32_t* Vs = Ks + 64 * AQS;          // [64][72]
    uint32_t* Ps = Vs + 64 * AVS;          // [64][68]

    const int tid  = threadIdx.x;
    const int wid  = tid >> 5;             // 0..3
    const int lane = tid & 31;
    const int g = lane >> 2;               // 0..7
    const int q = lane & 3;                // 0..3

    const int qt = blockIdx.x;             // 0..31
    const int bh = blockIdx.y;             // 0..63
    const int b  = bh >> 4;
    const int h  = bh & (NHEAD - 1);

    const int q0 = qt * 64;
    const int qr = wid << 4;               // warp's row base in tile
    const float NEG = -1e30f;

    // load Q tile (fp32 -> tf32)
    for (int i = tid; i < 1024; i += 128) {
        int row = i >> 4, c4 = (i & 15) << 2;
        float4 v = *(const float4*)(g_qkv
            + (size_t)(b * S_LEN + q0 + row) * (3 * DMODEL) + h * HD + c4);
        uint4 o;
        o.x = f32_to_tf32(v.x); o.y = f32_to_tf32(v.y);
        o.z = f32_to_tf32(v.z); o.w = f32_to_tf32(v.w);
        *(uint4*)&Qs[row * AQS + c4] = o;
    }

    float O[8][4];
    #pragma unroll
    for (int ni = 0; ni < 8; ni++)
        #pragma unroll
        for (int r = 0; r < 4; r++) O[ni][r] = 0.0f;
    float mrow0 = NEG, mrow1 = NEG, lrow0 = 0.0f, lrow1 = 0.0f;

    for (int kt = 0; kt <= qt; kt++) {
        const int k0 = kt * 64;
        __syncthreads();   // all warps done reading Ks/Vs from prev iter
        for (int i = tid; i < 1024; i += 128) {
            int row = i >> 4, c4 = (i & 15) << 2;
            const float* base = g_qkv
                + (size_t)(b * S_LEN + k0 + row) * (3 * DMODEL)
                + DMODEL + h * HD + c4;
            float4 kv = *(const float4*)base;
            float4 vv = *(const float4*)(base + DMODEL);
            uint4 ok, ov;
            ok.x = f32_to_tf32(kv.x); ok.y = f32_to_tf32(kv.y);
            ok.z = f32_to_tf32(kv.z); ok.w = f32_to_tf32(kv.w);
            ov.x = f32_to_tf32(vv.x); ov.y = f32_to_tf32(vv.y);
            ov.z = f32_to_tf32(vv.z); ov.w = f32_to_tf32(vv.w);
            *(uint4*)&Ks[row * AQS + c4] = ok;
            *(uint4*)&Vs[row * AVS + c4] = ov;
        }
        __syncthreads();

        // S = Q @ K^T  (warp: 16 x 64, K-dim = hd 64)
        float s[8][4];
        #pragma unroll
        for (int ni = 0; ni < 8; ni++)
            #pragma unroll
            for (int r = 0; r < 4; r++) s[ni][r] = 0.0f;

        #pragma unroll
        for (int k8 = 0; k8 < 64; k8 += 8) {
            uint32_t a[4];
            a[0] = Qs[(qr + g) * AQS + k8 + q];
            a[1] = Qs[(qr + g + 8) * AQS + k8 + q];
            a[2] = Qs[(qr + g) * AQS + k8 + q + 4];
            a[3] = Qs[(qr + g + 8) * AQS + k8 + q + 4];
            #pragma unroll
            for (int ni = 0; ni < 8; ni++) {
                uint32_t bb[2];
                bb[0] = Ks[(ni * 8 + g) * AQS + k8 + q];
                bb[1] = Ks[(ni * 8 + g) * AQS + k8 + q + 4];
                mma_tf32(s[ni], a, bb);
            }
        }

        // scale + causal mask (diagonal tile only)
        #pragma unroll
        for (int ni = 0; ni < 8; ni++)
            #pragma unroll
            for (int r = 0; r < 4; r++) s[ni][r] *= 0.125f;
        if (kt == qt) {
            int r0 = qr + g, r1 = qr + g + 8;
            #pragma unroll
            for (int ni = 0; ni < 8; ni++) {
                int c = ni * 8 + (q << 1);
                if (c > r0)     s[ni][0] = NEG;
                if (c + 1 > r0) s[ni][1] = NEG;
                if (c > r1)     s[ni][2] = NEG;
                if (c + 1 > r1) s[ni][3] = NEG;
            }
        }

        // online softmax (rows g and g+8; reduce over 4 q-lanes)
        float mx0 = NEG, mx1 = NEG;
        #pragma unroll
        for (int ni = 0; ni < 8; ni++) {
            mx0 = fmaxf(mx0, fmaxf(s[ni][0], s[ni][1]));
            mx1 = fmaxf(mx1, fmaxf(s[ni][2], s[ni][3]));
        }
        mx0 = fmaxf(mx0, __shfl_xor_sync(0xffffffffu, mx0, 1));
        mx0 = fmaxf(mx0, __shfl_xor_sync(0xffffffffu, mx0, 2));
        mx1 = fmaxf(mx1, __shfl_xor_sync(0xffffffffu, mx1, 1));
        mx1 = fmaxf(mx1, __shfl_xor_sync(0xffffffffu, mx1, 2));

        float mn0 = fmaxf(mrow0, mx0), mn1 = fmaxf(mrow1, mx1);
        float corr0 = __expf(mrow0 - mn0), corr1 = __expf(mrow1 - mn1);
        float sum0 = 0.0f, sum1 = 0.0f;
        #pragma unroll
        for (int ni = 0; ni < 8; ni++) {
            s[ni][0] = __expf(s[ni][0] - mn0);
            s[ni][1] = __expf(s[ni][1] - mn0);
            s[ni][2] = __expf(s[ni][2] - mn1);
            s[ni][3] = __expf(s[ni][3] - mn1);
            sum0 += s[ni][0] + s[ni][1];
            sum1 += s[ni][2] + s[ni][3];
        }
        sum0 += __shfl_xor_sync(0xffffffffu, sum0, 1);
        sum0 += __shfl_xor_sync(0xffffffffu, sum0, 2);
        sum1 += __shfl_xor_sync(0xffffffffu, sum1, 1);
        sum1 += __shfl_xor_sync(0xffffffffu, sum1, 2);
        lrow0 = lrow0 * corr0 + sum0;
        lrow1 = lrow1 * corr1 + sum1;
        mrow0 = mn0; mrow1 = mn1;
        #pragma unroll
        for (int ni = 0; ni < 8; ni++) {
            O[ni][0] *= corr0; O[ni][1] *= corr0;
            O[ni][2] *= corr1; O[ni][3] *= corr1;
        }

        // P -> smem (tf32), warp-private stripe
        #pragma unroll
        for (int ni = 0; ni < 8; ni++) {
            int c = ni * 8 + (q << 1);
            uint2 p0, p1;
            p0.x = f32_to_tf32(s[ni][0]); p0.y = f32_to_tf32(s[ni][1]);
            p1.x = f32_to_tf32(s[ni][2]); p1.y = f32_to_tf32(s[ni][3]);
            *(uint2*)&Ps[(qr + g) * AQS + c]     = p0;
            *(uint2*)&Ps[(qr + g + 8) * AQS + c] = p1;
        }
        __syncwarp();

        // O += P @ V  (warp: 16 x 64, K-dim = 64 keys)
        #pragma unroll
        for (int k8 = 0; k8 < 64; k8 += 8) {
            uint32_t a[4];
            a[0] = Ps[(qr + g) * AQS + k8 + q];
            a[1] = Ps[(qr + g + 8) * AQS + k8 + q];
            a[2] = Ps[(qr + g) * AQS + k8 + q + 4];
            a[3] = Ps[(qr + g + 8) * AQS + k8 + q + 4];
            #pragma unroll
            for (int ni = 0; ni < 8; ni++) {
                uint32_t bb[2];
                bb[0] = Vs[(k8 + q) * AVS + ni * 8 + g];
                bb[1] = Vs[(k8 + q + 4) * AVS + ni * 8 + g];
                mma_tf32(O[ni], a, bb);
            }
        }
    }

    // normalize + store as tf32 (proj GEMM input)
    float inv0 = 1.0f / lrow0, inv1 = 1.0f / lrow1;
    int r0 = q0 + qr + g, r1 = r0 + 8;
    uint32_t* d0 = g_attn + (size_t)(b * S_LEN + r0) * DMODEL + h * HD;
    uint32_t* d1 = g_attn + (size_t)(b * S_LEN + r1) * DMODEL + h * HD;
    #pragma unroll
    for (int ni = 0; ni < 8; ni++) {
        int c = ni * 8 + (q << 1);
        uint2 o0, o1;
        o0.x = f32_to_tf32(O[ni][0] * inv0); o0.y = f32_to_tf32(O[ni][1] * inv0);
        o1.x = f32_to_tf32(O[ni][2] * inv1); o1.y = f32_to_tf32(O[ni][3] * inv1);
        *(uint2*)&d0[c] = o0;
        *(uint2*)&d1[c] = o1;
    }
}

// ---------------------------------------------------------------------------
// kernel_launch: x, w_qkv, b_qkv, w_proj, b_proj
// ---------------------------------------------------------------------------
extern "C" void kernel_launch(void* const* d_in, const int* in_sizes, int n_in,
                              void* d_out, int out_size)
{
    const float* x      = (const float*)d_in[0];
    const float* w_qkv  = (const float*)d_in[1];
    const float* b_qkv  = (const float*)d_in[2];
    const float* w_proj = (const float*)d_in[3];
    const float* b_proj = (const float*)d_in[4];
    float* out = (float*)d_out;

    void *x_t, *wqkv_t, *wproj_t, *qkv, *attn;
    cudaGetSymbolAddress(&x_t, g_x_t);
    cudaGetSymbolAddress(&wqkv_t, g_wqkv_t);
    cudaGetSymbolAddress(&wproj_t, g_wproj_t);
    cudaGetSymbolAddress(&qkv, g_qkv);
    cudaGetSymbolAddress(&attn, g_attn);

    cudaFuncSetAttribute(attn_mma_kernel,
                         cudaFuncAttributeMaxDynamicSharedMemorySize,
                         ATTN_SMEM_BYTES);

    // 0) precision-preserving tf32 conversions (cvt.rna)
    {
        int n4x = MTOK * DMODEL / 4;
        cvt_tf32_kernel<<<(n4x + 255) / 256, 256>>>((const float4*)x, (uint4*)x_t, n4x);
        int n4q = DMODEL * 3 * DMODEL / 4;
        cvt_tf32_kernel<<<(n4q + 255) / 256, 256>>>((const float4*)w_qkv, (uint4*)wqkv_t, n4q);
        int n4p = DMODEL * DMODEL / 4;
        cvt_tf32_kernel<<<(n4p + 255) / 256, 256>>>((const float4*)w_proj, (uint4*)wproj_t, n4p);
    }

    // 1) QKV projection: [8192,1024] @ [1024,3072] + b
    {
        dim3 grid(3 * DMODEL / 128, MTOK / 128);
        tf32_gemm_kernel<<<grid, 256>>>(
            (const uint32_t*)x_t, (const uint32_t*)wqkv_t, b_qkv, (float*)qkv,
            MTOK, 3 * DMODEL, DMODEL);
    }

    // 2) causal flash attention on tensor cores
    {
        dim3 grid(S_LEN / 64, BATCH * NHEAD);
        attn_mma_kernel<<<grid, 128, ATTN_SMEM_BYTES>>>();
    }

    // 3) output projection: [8192,1024] @ [1024,1024] + b
    {
        dim3 grid(DMODEL / 128, MTOK / 128);
        tf32_gemm_kernel<<<grid, 256>>>(
            (const uint32_t*)attn, (const uint32_t*)wproj_t, b_proj, out,
            MTOK, DMODEL, DMODEL);
    }
}

// round 5
// speedup vs baseline: 2.9906x; 1.1629x over previous
#include <cuda_runtime.h>
#include <math.h>
#include <stdint.h>

// Problem shape (fixed by the dataset)
#define BATCH   4
#define S_LEN   2048
#define DMODEL  1024
#define NHEAD   16
#define HD      64
#define MTOK    (BATCH * S_LEN)        // 8192 token rows

// ---------------------------------------------------------------------------
// Scratch (device globals: allocation-free)
// ---------------------------------------------------------------------------
__device__ __align__(16) uint32_t g_x_t[(size_t)MTOK * DMODEL];
__device__ __align__(16) uint32_t g_wqkv_t[(size_t)DMODEL * 3 * DMODEL];
__device__ __align__(16) uint32_t g_wproj_t[(size_t)DMODEL * DMODEL];
__device__ __align__(16) float    g_qkv[(size_t)MTOK * 3 * DMODEL];
__device__ __align__(16) uint32_t g_attn[(size_t)MTOK * DMODEL];

__device__ __forceinline__ uint32_t f32_to_tf32(float v) {
    uint32_t b;
    asm("cvt.rna.tf32.f32 %0, %1;" : "=r"(b) : "f"(v));
    return b;
}

__device__ __forceinline__ void mma_tf32(float* c, const uint32_t* a,
                                         const uint32_t* b) {
    asm volatile(
        "mma.sync.aligned.m16n8k8.row.col.f32.tf32.tf32.f32 "
        "{%0,%1,%2,%3}, {%4,%5,%6,%7}, {%8,%9}, {%0,%1,%2,%3};"
        : "+f"(c[0]), "+f"(c[1]), "+f"(c[2]), "+f"(c[3])
        : "r"(a[0]), "r"(a[1]), "r"(a[2]), "r"(a[3]), "r"(b[0]), "r"(b[1]));
}

__device__ __forceinline__ uint32_t smem_u32(const void* p) {
    uint32_t a;
    asm("{ .reg .u64 t; cvta.to.shared.u64 t, %1; cvt.u32.u64 %0, t; }"
        : "=r"(a) : "l"(p));
    return a;
}
__device__ __forceinline__ void cp_async16(uint32_t dst, const void* src) {
    asm volatile("cp.async.cg.shared.global [%0], [%1], 16;"
                 :: "r"(dst), "l"(src));
}
#define CP_COMMIT()  asm volatile("cp.async.commit_group;" ::: "memory")
#define CP_WAIT1()   asm volatile("cp.async.wait_group 1;" ::: "memory")

// ---------------------------------------------------------------------------
// tf32 tensor-core GEMM, cp.async 3-stage pipeline.
// C[M,N] = A[M,K] @ B[K,N] + bias[N]
// Block 128x256, BK=16, 256 threads, 8 warps (2m x 4n), warp tile 64x64.
// As: m-major [128][20] (pad 4 -> frag bank = 20g+q, conflict-free)
// Bs: k-major [16][264] (pad 8 -> frag bank = 8q+g, conflict-free)
// ---------------------------------------------------------------------------
#define GBM 128
#define GBN 256
#define GBK 16
#define ASTR 20
#define BSTR 264
#define A_TW (128 * ASTR)            // 2560 words
#define B_TW (GBK * BSTR)            // 4224 words
#define STG_W (A_TW + B_TW)          // 6784 words
#define GEMM_SMEM_BYTES (3 * STG_W * 4)   // 81408 B

__global__ __launch_bounds__(256, 1) void tf32_gemm_kernel(
    const uint32_t* __restrict__ A, const uint32_t* __restrict__ B,
    const float* __restrict__ bias, float* __restrict__ C,
    int M, int N, int K)
{
    extern __shared__ uint32_t smw[];
    const uint32_t smb = smem_u32(smw);

    const int tid  = threadIdx.x;
    const int wid  = tid >> 5;
    const int lane = tid & 31;
    const int g = lane >> 2;          // 0..7
    const int q = lane & 3;           // 0..3

    const int wm = (wid & 1) << 6;    // 0 or 64
    const int wn = (wid >> 1) << 6;   // 0,64,128,192

    const int bm = blockIdx.y * GBM;
    const int bn = blockIdx.x * GBN;
    const int NT = K / GBK;

    // cp.async task assignments
    const int a_row = tid >> 2;           // 0..63 (+64 for r=1)
    const int a_ch  = (tid & 3) << 2;     // word offset 0,4,8,12
    const int b_kr  = tid >> 6;           // 0..3 (+4,+8,+12 for r)
    const int b_ch  = (tid & 63) << 2;    // 0..252

    // issue one stage's loads
    auto issue = [&](int s, int kt) {
        uint32_t sb = smb + (uint32_t)(s * STG_W) * 4;
        #pragma unroll
        for (int r = 0; r < 2; r++) {
            int row = a_row + (r << 6);
            cp_async16(sb + (uint32_t)(row * ASTR + a_ch) * 4,
                       A + (size_t)(bm + row) * K + kt * GBK + a_ch);
        }
        uint32_t bb = sb + (uint32_t)A_TW * 4;
        #pragma unroll
        for (int r = 0; r < 4; r++) {
            int kr = b_kr + (r << 2);
            cp_async16(bb + (uint32_t)(kr * BSTR + b_ch) * 4,
                       B + (size_t)(kt * GBK + kr) * N + bn + b_ch);
        }
    };

    float acc[4][8][4];
    #pragma unroll
    for (int mi = 0; mi < 4; mi++)
        #pragma unroll
        for (int ni = 0; ni < 8; ni++)
            #pragma unroll
            for (int r = 0; r < 4; r++) acc[mi][ni][r] = 0.0f;

    issue(0, 0); CP_COMMIT();
    issue(1, 1); CP_COMMIT();

    for (int kt = 0; kt < NT; kt++) {
        CP_WAIT1();
        __syncthreads();
        if (kt + 2 < NT) issue((kt + 2) % 3, kt + 2);
        CP_COMMIT();

        const uint32_t* As = smw + (kt % 3) * STG_W;
        const uint32_t* Bs = As + A_TW;

        #pragma unroll
        for (int k8 = 0; k8 < GBK; k8 += 8) {
            uint32_t af[4][4], bf[8][2];
            #pragma unroll
            for (int mi = 0; mi < 4; mi++) {
                const uint32_t* ar = As + (wm + (mi << 4) + g) * ASTR + k8 + q;
                af[mi][0] = ar[0];
                af[mi][1] = ar[8 * ASTR];
                af[mi][2] = ar[4];
                af[mi][3] = ar[8 * ASTR + 4];
            }
            #pragma unroll
            for (int ni = 0; ni < 8; ni++) {
                const uint32_t* br = Bs + (k8 + q) * BSTR + wn + (ni << 3) + g;
                bf[ni][0] = br[0];
                bf[ni][1] = br[4 * BSTR];
            }
            #pragma unroll
            for (int mi = 0; mi < 4; mi++)
                #pragma unroll
                for (int ni = 0; ni < 8; ni++)
                    mma_tf32(acc[mi][ni], af[mi], bf[ni]);
        }
    }

    // epilogue
    #pragma unroll
    for (int mi = 0; mi < 4; mi++) {
        int m = bm + wm + (mi << 4) + g;
        #pragma unroll
        for (int ni = 0; ni < 8; ni++) {
            int n = bn + wn + (ni << 3) + (q << 1);
            float2 bb = *(const float2*)&bias[n];
            float2 o0, o1;
            o0.x = acc[mi][ni][0] + bb.x;
            o0.y = acc[mi][ni][1] + bb.y;
            o1.x = acc[mi][ni][2] + bb.x;
            o1.y = acc[mi][ni][3] + bb.y;
            *(float2*)&C[(size_t)m * N + n]       = o0;
            *(float2*)&C[(size_t)(m + 8) * N + n] = o1;
        }
    }
}

// ---------------------------------------------------------------------------
// Elementwise fp32 -> tf32 (rna) conversion
// ---------------------------------------------------------------------------
__global__ void cvt_tf32_kernel(const float4* __restrict__ src,
                                uint4* __restrict__ dst, int n4)
{
    int i = blockIdx.x * blockDim.x + threadIdx.x;
    if (i < n4) {
        float4 v = src[i];
        uint4 o;
        o.x = f32_to_tf32(v.x); o.y = f32_to_tf32(v.y);
        o.z = f32_to_tf32(v.z); o.w = f32_to_tf32(v.w);
        dst[i] = o;
    }
}

// ---------------------------------------------------------------------------
// Flash attention on tensor cores (tf32 mma.sync), causal. (unchanged)
// ---------------------------------------------------------------------------
#define AQS 68
#define AVS 72
#define ATTN_SMEM_BYTES ((64*AQS*3 + 64*AVS) * 4)

__global__ __launch_bounds__(128) void attn_mma_kernel()
{
    extern __shared__ uint32_t smu[];
    uint32_t* Qs = smu;
    uint32_t* Ks = Qs + 64 * AQS;
    uint32_t* Vs = Ks + 64 * AQS;
    uint32_t* Ps = Vs + 64 * AVS;

    const int tid  = threadIdx.x;
    const int wid  = tid >> 5;
    const int lane = tid & 31;
    const int g = lane >> 2;
    const int q = lane & 3;

    const int qt = blockIdx.x;
    const int bh = blockIdx.y;
    const int b  = bh >> 4;
    const int h  = bh & (NHEAD - 1);

    const int q0 = qt * 64;
    const int qr = wid << 4;
    const float NEG = -1e30f;

    for (int i = tid; i < 1024; i += 128) {
        int row = i >> 4, c4 = (i & 15) << 2;
        float4 v = *(const float4*)(g_qkv
            + (size_t)(b * S_LEN + q0 + row) * (3 * DMODEL) + h * HD + c4);
        uint4 o;
        o.x = f32_to_tf32(v.x); o.y = f32_to_tf32(v.y);
        o.z = f32_to_tf32(v.z); o.w = f32_to_tf32(v.w);
        *(uint4*)&Qs[row * AQS + c4] = o;
    }

    float O[8][4];
    #pragma unroll
    for (int ni = 0; ni < 8; ni++)
        #pragma unroll
        for (int r = 0; r < 4; r++) O[ni][r] = 0.0f;
    float mrow0 = NEG, mrow1 = NEG, lrow0 = 0.0f, lrow1 = 0.0f;

    for (int kt = 0; kt <= qt; kt++) {
        const int k0 = kt * 64;
        __syncthreads();
        for (int i = tid; i < 1024; i += 128) {
            int row = i >> 4, c4 = (i & 15) << 2;
            const float* base = g_qkv
                + (size_t)(b * S_LEN + k0 + row) * (3 * DMODEL)
                + DMODEL + h * HD + c4;
            float4 kv = *(const float4*)base;
            float4 vv = *(const float4*)(base + DMODEL);
            uint4 ok, ov;
            ok.x = f32_to_tf32(kv.x); ok.y = f32_to_tf32(kv.y);
            ok.z = f32_to_tf32(kv.z); ok.w = f32_to_tf32(kv.w);
            ov.x = f32_to_tf32(vv.x); ov.y = f32_to_tf32(vv.y);
            ov.z = f32_to_tf32(vv.z); ov.w = f32_to_tf32(vv.w);
            *(uint4*)&Ks[row * AQS + c4] = ok;
            *(uint4*)&Vs[row * AVS + c4] = ov;
        }
        __syncthreads();

        float s[8][4];
        #pragma unroll
        for (int ni = 0; ni < 8; ni++)
            #pragma unroll
            for (int r = 0; r < 4; r++) s[ni][r] = 0.0f;

        #pragma unroll
        for (int k8 = 0; k8 < 64; k8 += 8) {
            uint32_t a[4];
            a[0] = Qs[(qr + g) * AQS + k8 + q];
            a[1] = Qs[(qr + g + 8) * AQS + k8 + q];
            a[2] = Qs[(qr + g) * AQS + k8 + q + 4];
            a[3] = Qs[(qr + g + 8) * AQS + k8 + q + 4];
            #pragma unroll
            for (int ni = 0; ni < 8; ni++) {
                uint32_t bb[2];
                bb[0] = Ks[(ni * 8 + g) * AQS + k8 + q];
                bb[1] = Ks[(ni * 8 + g) * AQS + k8 + q + 4];
                mma_tf32(s[ni], a, bb);
            }
        }

        #pragma unroll
        for (int ni = 0; ni < 8; ni++)
            #pragma unroll
            for (int r = 0; r < 4; r++) s[ni][r] *= 0.125f;
        if (kt == qt) {
            int r0 = qr + g, r1 = qr + g + 8;
            #pragma unroll
            for (int ni = 0; ni < 8; ni++) {
                int c = ni * 8 + (q << 1);
                if (c > r0)     s[ni][0] = NEG;
                if (c + 1 > r0) s[ni][1] = NEG;
                if (c > r1)     s[ni][2] = NEG;
                if (c + 1 > r1) s[ni][3] = NEG;
            }
        }

        float mx0 = NEG, mx1 = NEG;
        #pragma unroll
        for (int ni = 0; ni < 8; ni++) {
            mx0 = fmaxf(mx0, fmaxf(s[ni][0], s[ni][1]));
            mx1 = fmaxf(mx1, fmaxf(s[ni][2], s[ni][3]));
        }
        mx0 = fmaxf(mx0, __shfl_xor_sync(0xffffffffu, mx0, 1));
        mx0 = fmaxf(mx0, __shfl_xor_sync(0xffffffffu, mx0, 2));
        mx1 = fmaxf(mx1, __shfl_xor_sync(0xffffffffu, mx1, 1));
        mx1 = fmaxf(mx1, __shfl_xor_sync(0xffffffffu, mx1, 2));

        float mn0 = fmaxf(mrow0, mx0), mn1 = fmaxf(mrow1, mx1);
        float corr0 = __expf(mrow0 - mn0), corr1 = __expf(mrow1 - mn1);
        float sum0 = 0.0f, sum1 = 0.0f;
        #pragma unroll
        for (int ni = 0; ni < 8; ni++) {
            s[ni][0] = __expf(s[ni][0] - mn0);
            s[ni][1] = __expf(s[ni][1] - mn0);
            s[ni][2] = __expf(s[ni][2] - mn1);
            s[ni][3] = __expf(s[ni][3] - mn1);
            sum0 += s[ni][0] + s[ni][1];
            sum1 += s[ni][2] + s[ni][3];
        }
        sum0 += __shfl_xor_sync(0xffffffffu, sum0, 1);
        sum0 += __shfl_xor_sync(0xffffffffu, sum0, 2);
        sum1 += __shfl_xor_sync(0xffffffffu, sum1, 1);
        sum1 += __shfl_xor_sync(0xffffffffu, sum1, 2);
        lrow0 = lrow0 * corr0 + sum0;
        lrow1 = lrow1 * corr1 + sum1;
        mrow0 = mn0; mrow1 = mn1;
        #pragma unroll
        for (int ni = 0; ni < 8; ni++) {
            O[ni][0] *= corr0; O[ni][1] *= corr0;
            O[ni][2] *= corr1; O[ni][3] *= corr1;
        }

        #pragma unroll
        for (int ni = 0; ni < 8; ni++) {
            int c = ni * 8 + (q << 1);
            uint2 p0, p1;
            p0.x = f32_to_tf32(s[ni][0]); p0.y = f32_to_tf32(s[ni][1]);
            p1.x = f32_to_tf32(s[ni][2]); p1.y = f32_to_tf32(s[ni][3]);
            *(uint2*)&Ps[(qr + g) * AQS + c]     = p0;
            *(uint2*)&Ps[(qr + g + 8) * AQS + c] = p1;
        }
        __syncwarp();

        #pragma unroll
        for (int k8 = 0; k8 < 64; k8 += 8) {
            uint32_t a[4];
            a[0] = Ps[(qr + g) * AQS + k8 + q];
            a[1] = Ps[(qr + g + 8) * AQS + k8 + q];
            a[2] = Ps[(qr + g) * AQS + k8 + q + 4];
            a[3] = Ps[(qr + g + 8) * AQS + k8 + q + 4];
            #pragma unroll
            for (int ni = 0; ni < 8; ni++) {
                uint32_t bb[2];
                bb[0] = Vs[(k8 + q) * AVS + ni * 8 + g];
                bb[1] = Vs[(k8 + q + 4) * AVS + ni * 8 + g];
                mma_tf32(O[ni], a, bb);
            }
        }
    }

    float inv0 = 1.0f / lrow0, inv1 = 1.0f / lrow1;
    int r0 = q0 + qr + g, r1 = r0 + 8;
    uint32_t* d0 = g_attn + (size_t)(b * S_LEN + r0) * DMODEL + h * HD;
    uint32_t* d1 = g_attn + (size_t)(b * S_LEN + r1) * DMODEL + h * HD;
    #pragma unroll
    for (int ni = 0; ni < 8; ni++) {
        int c = ni * 8 + (q << 1);
        uint2 o0, o1;
        o0.x = f32_to_tf32(O[ni][0] * inv0); o0.y = f32_to_tf32(O[ni][1] * inv0);
        o1.x = f32_to_tf32(O[ni][2] * inv1); o1.y = f32_to_tf32(O[ni][3] * inv1);
        *(uint2*)&d0[c] = o0;
        *(uint2*)&d1[c] = o1;
    }
}

// ---------------------------------------------------------------------------
// kernel_launch: x, w_qkv, b_qkv, w_proj, b_proj
// ---------------------------------------------------------------------------
extern "C" void kernel_launch(void* const* d_in, const int* in_sizes, int n_in,
                              void* d_out, int out_size)
{
    const float* x      = (const float*)d_in[0];
    const float* w_qkv  = (const float*)d_in[1];
    const float* b_qkv  = (const float*)d_in[2];
    const float* w_proj = (const float*)d_in[3];
    const float* b_proj = (const float*)d_in[4];
    float* out = (float*)d_out;

    void *x_t, *wqkv_t, *wproj_t, *qkv, *attn;
    cudaGetSymbolAddress(&x_t, g_x_t);
    cudaGetSymbolAddress(&wqkv_t, g_wqkv_t);
    cudaGetSymbolAddress(&wproj_t, g_wproj_t);
    cudaGetSymbolAddress(&qkv, g_qkv);
    cudaGetSymbolAddress(&attn, g_attn);

    cudaFuncSetAttribute(tf32_gemm_kernel,
                         cudaFuncAttributeMaxDynamicSharedMemorySize,
                         GEMM_SMEM_BYTES);
    cudaFuncSetAttribute(attn_mma_kernel,
                         cudaFuncAttributeMaxDynamicSharedMemorySize,
                         ATTN_SMEM_BYTES);

    // 0) precision-preserving tf32 conversions (cvt.rna)
    {
        int n4x = MTOK * DMODEL / 4;
        cvt_tf32_kernel<<<(n4x + 255) / 256, 256>>>((const float4*)x, (uint4*)x_t, n4x);
        int n4q = DMODEL * 3 * DMODEL / 4;
        cvt_tf32_kernel<<<(n4q + 255) / 256, 256>>>((const float4*)w_qkv, (uint4*)wqkv_t, n4q);
        int n4p = DMODEL * DMODEL / 4;
        cvt_tf32_kernel<<<(n4p + 255) / 256, 256>>>((const float4*)w_proj, (uint4*)wproj_t, n4p);
    }

    // 1) QKV projection: [8192,1024] @ [1024,3072] + b
    {
        dim3 grid(3 * DMODEL / GBN, MTOK / GBM);
        tf32_gemm_kernel<<<grid, 256, GEMM_SMEM_BYTES>>>(
            (const uint32_t*)x_t, (const uint32_t*)wqkv_t, b_qkv, (float*)qkv,
            MTOK, 3 * DMODEL, DMODEL);
    }

    // 2) causal flash attention on tensor cores
    {
        dim3 grid(S_LEN / 64, BATCH * NHEAD);
        attn_mma_kernel<<<grid, 128, ATTN_SMEM_BYTES>>>();
    }

    // 3) output projection: [8192,1024] @ [1024,1024] + b
    {
        dim3 grid(DMODEL / GBN, MTOK / GBM);
        tf32_gemm_kernel<<<grid, 256, GEMM_SMEM_BYTES>>>(
            (const uint32_t*)attn, (const uint32_t*)wproj_t, b_proj, out,
            MTOK, DMODEL, DMODEL);
    }
}